// round 1
// baseline (speedup 1.0000x reference)
#include <cuda_runtime.h>
#include <math.h>

#define TT  50
#define BB  1024
#define BEL 200
#define ST  30
#define ACT 8
#define EMB 1024

// ---- output layout (tuple flattened in reference return order) ----
static const size_t OFF_B  = 0;                                  // beliefs [50,1024,200]
static const size_t OFF_PS = (size_t)TT * BB * BEL;              // prior_states
static const size_t SZ30   = (size_t)TT * BB * ST;
static const size_t OFF_MP = OFF_PS + SZ30;                      // prior_means
static const size_t OFF_SP = OFF_MP + SZ30;                      // prior_std_devs
static const size_t OFF_PO = OFF_SP + SZ30;                      // posterior_states
static const size_t OFF_MQ = OFF_PO + SZ30;                      // posterior_means
static const size_t OFF_SQ = OFF_MQ + SZ30;                      // posterior_std_devs

// ---- device scratch (static: no allocations allowed) ----
__device__ float g_obs_proj[(size_t)TT * BB * BEL];   // obs @ W_bq_embed^T + b_bq  (41 MB)
__device__ float g_belief[BB * BEL];                  // belief carry
__device__ float g_post[BB * ST];                     // posterior-state carry
// transposed weights (coalesced reads: [k][out])
__device__ float g_WsaT[(ST + ACT) * BEL];   // 38 x 200
__device__ float g_WihT[BEL * 600];
__device__ float g_WhhT[BEL * 600];
__device__ float g_WbpT[BEL * BEL];
__device__ float g_WspT[BEL * 60];
__device__ float g_WbqbT[BEL * BEL];         // belief part of W_bq
__device__ float g_WbqeT[EMB * BEL];         // embed  part of W_bq
__device__ float g_WsqT[BEL * 60];

__device__ __forceinline__ float sigm(float x) { return 1.f / (1.f + expf(-x)); }
__device__ __forceinline__ float softplusf(float x) {
    return fmaxf(x, 0.f) + log1pf(expf(-fabsf(x)));
}

// ---------------------------------------------------------------------------
// Prep: transpose all weights into [k][out] layouts, split W_bq.
// ---------------------------------------------------------------------------
__global__ void k_prep(const float* __restrict__ W_sa, const float* __restrict__ W_ih,
                       const float* __restrict__ W_hh, const float* __restrict__ W_bp,
                       const float* __restrict__ W_sp, const float* __restrict__ W_bq,
                       const float* __restrict__ W_sq) {
    int idx = blockIdx.x * blockDim.x + threadIdx.x;
    // seg0: W_sa [200][38]
    if (idx < 200 * 38) { int h = idx / 38, k = idx - h * 38; g_WsaT[k * BEL + h] = W_sa[idx]; return; }
    idx -= 200 * 38;
    // seg1: W_ih [600][200]
    if (idx < 600 * 200) { int g = idx / 200, k = idx - g * 200; g_WihT[k * 600 + g] = W_ih[idx]; return; }
    idx -= 600 * 200;
    // seg2: W_hh [600][200]
    if (idx < 600 * 200) { int g = idx / 200, k = idx - g * 200; g_WhhT[k * 600 + g] = W_hh[idx]; return; }
    idx -= 600 * 200;
    // seg3: W_bp [200][200]
    if (idx < 200 * 200) { int h = idx / 200, k = idx - h * 200; g_WbpT[k * BEL + h] = W_bp[idx]; return; }
    idx -= 200 * 200;
    // seg4: W_sp [60][200]
    if (idx < 60 * 200) { int h = idx / 200, k = idx - h * 200; g_WspT[k * 60 + h] = W_sp[idx]; return; }
    idx -= 60 * 200;
    // seg5: W_bq [200][1224] split
    if (idx < 200 * 1224) {
        int h = idx / 1224, k = idx - h * 1224;
        float v = W_bq[idx];
        if (k < 200) g_WbqbT[k * BEL + h] = v;
        else         g_WbqeT[(size_t)(k - 200) * BEL + h] = v;
        return;
    }
    idx -= 200 * 1224;
    // seg6: W_sq [60][200]
    if (idx < 60 * 200) { int h = idx / 200, k = idx - h * 200; g_WsqT[k * 60 + h] = W_sq[idx]; return; }
}

// ---------------------------------------------------------------------------
// Hoisted GEMM: g_obs_proj[row][h] = sum_e obs[row][e] * W_bq[h][200+e] + b_bq[h]
// M=51200, N=200, K=1024. BM=64, BN=200 (full), BK=16. 256 threads:
// thread = (r in 0..31, colgroup in 0..7), owns rows {r, r+32} x 25 cols.
// B reads are warp-uniform (broadcast), A reads conflict-free (stride 17).
// ---------------------------------------------------------------------------
__global__ __launch_bounds__(256) void k_obs_gemm(const float* __restrict__ A,
                                                  const float* __restrict__ b_bq) {
    __shared__ __align__(16) float As[64 * 17];
    __shared__ __align__(16) float Bs[16 * 200];
    const int tid = threadIdx.x;
    const size_t row0 = (size_t)blockIdx.x * 64;
    const int r = tid & 31;
    const int cbase = (tid >> 5) * 25;

    float acc0[25], acc1[25];
#pragma unroll
    for (int c = 0; c < 25; c++) { acc0[c] = 0.f; acc1[c] = 0.f; }

    const int li = tid >> 2;          // A row within tile (0..63)
    const int lk = (tid & 3) * 4;     // A k offset within tile

    for (int kt = 0; kt < EMB; kt += 16) {
        float4 va = *(const float4*)&A[(row0 + li) * EMB + kt + lk];
        As[li * 17 + lk + 0] = va.x;
        As[li * 17 + lk + 1] = va.y;
        As[li * 17 + lk + 2] = va.z;
        As[li * 17 + lk + 3] = va.w;
        for (int idx = tid; idx < 800; idx += 256) {   // 16*200/4 float4s
            int k = idx / 50;
            int c4 = (idx - k * 50) * 4;
            *(float4*)&Bs[k * 200 + c4] =
                *(const float4*)&g_WbqeT[(size_t)(kt + k) * BEL + c4];
        }
        __syncthreads();
#pragma unroll
        for (int k = 0; k < 16; k++) {
            float a0 = As[r * 17 + k];
            float a1 = As[(r + 32) * 17 + k];
#pragma unroll
            for (int c = 0; c < 25; c++) {
                float bv = Bs[k * 200 + cbase + c];
                acc0[c] = fmaf(a0, bv, acc0[c]);
                acc1[c] = fmaf(a1, bv, acc1[c]);
            }
        }
        __syncthreads();
    }
#pragma unroll
    for (int c = 0; c < 25; c++) {
        float bias = b_bq[cbase + c];
        g_obs_proj[(row0 + r) * BEL + cbase + c]        = acc0[c] + bias;
        g_obs_proj[(row0 + r + 32) * BEL + cbase + c]   = acc1[c] + bias;
    }
}

// ---------------------------------------------------------------------------
// Step kernel 1: hidden = relu([s,a] @ W_sa^T + b_sa); belief = GRU(hidden, belief)
// 128 blocks x 256 threads; each block owns 8 batch rows; thread j = belief col.
// ---------------------------------------------------------------------------
__global__ __launch_bounds__(256) void k_gru(int t,
    const float* __restrict__ actions, const float* __restrict__ nonterm,
    const float* __restrict__ prev_state, const float* __restrict__ prev_belief,
    const float* __restrict__ b_sa, const float* __restrict__ b_ih,
    const float* __restrict__ b_hh, float* __restrict__ out) {
    __shared__ float s_sh[8][ST];
    __shared__ float a_sh[8][ACT];
    __shared__ float bel_sh[8][BEL];
    __shared__ float hid_sh[8][BEL];

    const int tid = threadIdx.x;
    const int b0 = blockIdx.x * 8;
    const float* post_src   = (t == 0) ? prev_state  : g_post;
    const float* belief_src = (t == 0) ? prev_belief : g_belief;

    for (int idx = tid; idx < 8 * BEL; idx += 256) {
        int bb = idx / BEL, j = idx - bb * BEL;
        bel_sh[bb][j] = belief_src[(size_t)(b0 + bb) * BEL + j];
    }
    for (int idx = tid; idx < 8 * ST; idx += 256) {
        int bb = idx / ST, i = idx - bb * ST;
        s_sh[bb][i] = post_src[(size_t)(b0 + bb) * ST + i] * nonterm[(size_t)t * BB + b0 + bb];
    }
    if (tid < 64) {
        int bb = tid >> 3, i = tid & 7;
        a_sh[bb][i] = actions[((size_t)t * BB + b0 + bb) * ACT + i];
    }
    __syncthreads();

    const int j = tid;
    if (j < BEL) {
        float h[8];
        float bsa = b_sa[j];
#pragma unroll
        for (int bb = 0; bb < 8; bb++) h[bb] = bsa;
        for (int i = 0; i < ST; i++) {
            float w = g_WsaT[i * BEL + j];
#pragma unroll
            for (int bb = 0; bb < 8; bb++) h[bb] = fmaf(s_sh[bb][i], w, h[bb]);
        }
#pragma unroll
        for (int i = 0; i < ACT; i++) {
            float w = g_WsaT[(ST + i) * BEL + j];
#pragma unroll
            for (int bb = 0; bb < 8; bb++) h[bb] = fmaf(a_sh[bb][i], w, h[bb]);
        }
#pragma unroll
        for (int bb = 0; bb < 8; bb++) hid_sh[bb][j] = fmaxf(h[bb], 0.f);
    }
    __syncthreads();

    if (j < BEL) {
        float air[8] = {0}, aiz[8] = {0}, ain[8] = {0};
        float ahr[8] = {0}, ahz[8] = {0}, ahn[8] = {0};
        const float* wi = g_WihT + j;
        const float* wh = g_WhhT + j;
        for (int k = 0; k < BEL; k++) {
            float wir = wi[k * 600], wiz = wi[k * 600 + 200], win = wi[k * 600 + 400];
            float whr = wh[k * 600], whz = wh[k * 600 + 200], whn = wh[k * 600 + 400];
#pragma unroll
            for (int bb = 0; bb < 8; bb++) {
                float hv = hid_sh[bb][k], bv = bel_sh[bb][k];
                air[bb] = fmaf(hv, wir, air[bb]);
                aiz[bb] = fmaf(hv, wiz, aiz[bb]);
                ain[bb] = fmaf(hv, win, ain[bb]);
                ahr[bb] = fmaf(bv, whr, ahr[bb]);
                ahz[bb] = fmaf(bv, whz, ahz[bb]);
                ahn[bb] = fmaf(bv, whn, ahn[bb]);
            }
        }
        float bir = b_ih[j], biz = b_ih[200 + j], binn = b_ih[400 + j];
        float bhr = b_hh[j], bhz = b_hh[200 + j], bhn  = b_hh[400 + j];
#pragma unroll
        for (int bb = 0; bb < 8; bb++) {
            float r = sigm(air[bb] + bir + ahr[bb] + bhr);
            float z = sigm(aiz[bb] + biz + ahz[bb] + bhz);
            float n = tanhf(ain[bb] + binn + r * (ahn[bb] + bhn));
            float bn = (1.f - z) * n + z * bel_sh[bb][j];
            g_belief[(size_t)(b0 + bb) * BEL + j] = bn;
            out[OFF_B + ((size_t)t * BB + b0 + bb) * BEL + j] = bn;
        }
    }
}

// ---------------------------------------------------------------------------
// Step kernel 2: prior + posterior heads (fused).
// hp = relu(belief@W_bp^T+b_bp); [mp|sp] = hp@W_sp^T+b_sp
// hq = relu(belief@W_bqb^T + obs_proj); [mq|sq] = hq@W_sq^T+b_sq
// ---------------------------------------------------------------------------
__global__ __launch_bounds__(256) void k_pq(int t,
    const float* __restrict__ noise_p, const float* __restrict__ noise_q,
    const float* __restrict__ b_bp, const float* __restrict__ b_sp,
    const float* __restrict__ b_sq, float* __restrict__ out) {
    __shared__ float bel_sh[8][BEL];
    __shared__ float hp_sh[8][BEL];
    __shared__ float hq_sh[8][BEL];
    __shared__ float so_sh[8][120];

    const int tid = threadIdx.x;
    const int b0 = blockIdx.x * 8;

    for (int idx = tid; idx < 8 * BEL; idx += 256) {
        int bb = idx / BEL, j = idx - bb * BEL;
        bel_sh[bb][j] = g_belief[(size_t)(b0 + bb) * BEL + j];
    }
    __syncthreads();

    const int j = tid;
    if (j < BEL) {
        float ap[8] = {0}, aq[8] = {0};
        const float* wp = g_WbpT + j;
        const float* wq = g_WbqbT + j;
        for (int k = 0; k < BEL; k++) {
            float wpv = wp[k * BEL], wqv = wq[k * BEL];
#pragma unroll
            for (int bb = 0; bb < 8; bb++) {
                float bv = bel_sh[bb][k];
                ap[bb] = fmaf(bv, wpv, ap[bb]);
                aq[bb] = fmaf(bv, wqv, aq[bb]);
            }
        }
        float bpv = b_bp[j];
#pragma unroll
        for (int bb = 0; bb < 8; bb++) {
            hp_sh[bb][j] = fmaxf(ap[bb] + bpv, 0.f);
            hq_sh[bb][j] = fmaxf(aq[bb] + g_obs_proj[((size_t)t * BB + b0 + bb) * BEL + j], 0.f);
        }
    }
    __syncthreads();

    if (tid < 120) {
        bool pr = tid < 60;
        int j2 = pr ? tid : tid - 60;
        const float* Wt = pr ? g_WspT : g_WsqT;
        float acc[8] = {0};
        for (int k = 0; k < BEL; k++) {
            float w = Wt[k * 60 + j2];
#pragma unroll
            for (int bb = 0; bb < 8; bb++) {
                float v = pr ? hp_sh[bb][k] : hq_sh[bb][k];
                acc[bb] = fmaf(v, w, acc[bb]);
            }
        }
        float bias = pr ? b_sp[j2] : b_sq[j2];
#pragma unroll
        for (int bb = 0; bb < 8; bb++) so_sh[bb][tid] = acc[bb] + bias;
    }
    __syncthreads();

    if (tid < 60) {
        bool pr = tid < 30;
        int i = pr ? tid : tid - 30;
#pragma unroll
        for (int bb = 0; bb < 8; bb++) {
            size_t gidx = ((size_t)t * BB + b0 + bb) * ST + i;
            if (pr) {
                float mp  = so_sh[bb][i];
                float spv = softplusf(so_sh[bb][30 + i]) + 0.1f;
                out[OFF_MP + gidx] = mp;
                out[OFF_SP + gidx] = spv;
                out[OFF_PS + gidx] = fmaf(spv, noise_p[gidx], mp);
            } else {
                float mq  = so_sh[bb][60 + i];
                float sqv = softplusf(so_sh[bb][90 + i]) + 0.1f;
                float po  = fmaf(sqv, noise_q[gidx], mq);
                out[OFF_MQ + gidx] = mq;
                out[OFF_SQ + gidx] = sqv;
                out[OFF_PO + gidx] = po;
                g_post[(size_t)(b0 + bb) * ST + i] = po;
            }
        }
    }
}

// ---------------------------------------------------------------------------
extern "C" void kernel_launch(void* const* d_in, const int* in_sizes, int n_in,
                              void* d_out, int out_size) {
    const float* prev_state   = (const float*)d_in[0];
    const float* actions      = (const float*)d_in[1];
    const float* prev_belief  = (const float*)d_in[2];
    const float* observations = (const float*)d_in[3];
    const float* nonterm      = (const float*)d_in[4];
    const float* noise_p      = (const float*)d_in[5];
    const float* noise_q      = (const float*)d_in[6];
    const float* W_sa = (const float*)d_in[7];  const float* b_sa = (const float*)d_in[8];
    const float* W_ih = (const float*)d_in[9];  const float* b_ih = (const float*)d_in[10];
    const float* W_hh = (const float*)d_in[11]; const float* b_hh = (const float*)d_in[12];
    const float* W_bp = (const float*)d_in[13]; const float* b_bp = (const float*)d_in[14];
    const float* W_sp = (const float*)d_in[15]; const float* b_sp = (const float*)d_in[16];
    const float* W_bq = (const float*)d_in[17]; const float* b_bq = (const float*)d_in[18];
    const float* W_sq = (const float*)d_in[19]; const float* b_sq = (const float*)d_in[20];
    float* out = (float*)d_out;

    (void)in_sizes; (void)n_in; (void)out_size;

    // 1) weight transposes
    k_prep<<<(556400 + 255) / 256, 256>>>(W_sa, W_ih, W_hh, W_bp, W_sp, W_bq, W_sq);
    // 2) hoisted observation GEMM (parallel over all timesteps)
    k_obs_gemm<<<(TT * BB) / 64, 256>>>(observations, b_bq);
    // 3) sequential scan
    for (int t = 0; t < TT; t++) {
        k_gru<<<BB / 8, 256>>>(t, actions, nonterm, prev_state, prev_belief,
                               b_sa, b_ih, b_hh, out);
        k_pq<<<BB / 8, 256>>>(t, noise_p, noise_q, b_bp, b_sp, b_sq, out);
    }
}

// round 2
// speedup vs baseline: 1.6749x; 1.6749x over previous
#include <cuda_runtime.h>
#include <math.h>

#define TT  50
#define BB  1024
#define BEL 200
#define ST  30
#define ACT 8
#define EMB 1024

// ---- output layout (tuple flattened in reference return order) ----
static const size_t OFF_B  = 0;
static const size_t OFF_PS = (size_t)TT * BB * BEL;
static const size_t SZ30   = (size_t)TT * BB * ST;
static const size_t OFF_MP = OFF_PS + SZ30;
static const size_t OFF_SP = OFF_MP + SZ30;
static const size_t OFF_PO = OFF_SP + SZ30;
static const size_t OFF_MQ = OFF_PO + SZ30;
static const size_t OFF_SQ = OFF_MQ + SZ30;

// ---- device scratch ----
__device__ __align__(16) float g_obs_proj[(size_t)TT * BB * BEL];  // 41 MB
// float4-packed (along k) transposed weights
__device__ __align__(16) float g_Wg4[50 * 1200 * 4];   // [k4][g<600:ih | 600+g:hh][4]
__device__ __align__(16) float g_Wsa4[10 * 200 * 4];   // [k4][j][4], k padded 38->40
__device__ __align__(16) float g_Wh4[50 * 400 * 4];    // [k4][g<200:Wbp | Wbq_belief][4]
__device__ __align__(16) float g_Wo4[50 * 120 * 4];    // [k4][g<60:Wsp | Wsq][4]
__device__ __align__(16) float g_WbqeT[(size_t)EMB * BEL];  // [e][h] embed part of W_bq

typedef unsigned long long u64;

__device__ __forceinline__ void ffma2(u64& acc, u64 a, u64 b) {
    asm("fma.rn.f32x2 %0, %1, %2, %0;" : "+l"(acc) : "l"(a), "l"(b));
}
__device__ __forceinline__ float hsum2(u64 v) {
    float lo, hi;
    asm("mov.b64 {%0,%1}, %2;" : "=f"(lo), "=f"(hi) : "l"(v));
    return lo + hi;
}
__device__ __forceinline__ float sigm(float x) { return 1.f / (1.f + __expf(-x)); }
__device__ __forceinline__ float tanhfast(float x) { return 1.f - 2.f / (__expf(2.f * x) + 1.f); }
__device__ __forceinline__ float softplusf(float x) {
    return fmaxf(x, 0.f) + log1pf(__expf(-fabsf(x)));
}

// ---------------------------------------------------------------------------
// Prep: build packed weight layouts.
// ---------------------------------------------------------------------------
#define PREP_N (240000 + 8000 + 80000 + 24000 + 204800)
__global__ void k_prep(const float* __restrict__ W_sa, const float* __restrict__ W_ih,
                       const float* __restrict__ W_hh, const float* __restrict__ W_bp,
                       const float* __restrict__ W_sp, const float* __restrict__ W_bq,
                       const float* __restrict__ W_sq) {
    int idx = blockIdx.x * blockDim.x + threadIdx.x;
    if (idx < 240000) {  // Wg4
        int c = idx & 3, rest = idx >> 2;
        int g = rest % 1200, k4 = rest / 1200, k = 4 * k4 + c;
        g_Wg4[idx] = (g < 600) ? W_ih[g * 200 + k] : W_hh[(g - 600) * 200 + k];
        return;
    }
    idx -= 240000;
    if (idx < 8000) {  // Wsa4
        int c = idx & 3, rest = idx >> 2;
        int j = rest % 200, k4 = rest / 200, k = 4 * k4 + c;
        g_Wsa4[idx] = (k < 38) ? W_sa[j * 38 + k] : 0.f;
        return;
    }
    idx -= 8000;
    if (idx < 80000) {  // Wh4
        int c = idx & 3, rest = idx >> 2;
        int g = rest % 400, k4 = rest / 400, k = 4 * k4 + c;
        g_Wh4[idx] = (g < 200) ? W_bp[g * 200 + k] : W_bq[(g - 200) * 1224 + k];
        return;
    }
    idx -= 80000;
    if (idx < 24000) {  // Wo4
        int c = idx & 3, rest = idx >> 2;
        int g = rest % 120, k4 = rest / 120, k = 4 * k4 + c;
        g_Wo4[idx] = (g < 60) ? W_sp[g * 200 + k] : W_sq[(g - 60) * 200 + k];
        return;
    }
    idx -= 24000;
    if (idx < 204800) {  // WbqeT
        int e = idx / 200, h = idx - e * 200;
        g_WbqeT[(size_t)e * 200 + h] = W_bq[h * 1224 + 200 + e];
    }
}

// ---------------------------------------------------------------------------
// Hoisted obs GEMM with f32x2: g_obs_proj = obs @ WbqeT + b_bq
// M=51200, N=200, K=1024. 800 blocks x 512 threads; thread = 1 row x 25 cols.
// ---------------------------------------------------------------------------
__global__ __launch_bounds__(512) void k_obs_gemm(const float* __restrict__ A,
                                                  const float* __restrict__ b_bq) {
    __shared__ __align__(16) float As[64 * 18];
    __shared__ __align__(16) float Bs[200 * 18];   // transposed [h][e] within tile
    const int tid = threadIdx.x;
    const size_t row0 = (size_t)blockIdx.x * 64;
    const int r = tid & 63;
    const int cbase = (tid >> 6) * 25;

    u64 acc[25];
#pragma unroll
    for (int c = 0; c < 25; c++) acc[c] = 0ULL;

    const int li = tid >> 3, lk = (tid & 7) * 2;
    for (int kt = 0; kt < EMB; kt += 16) {
        float2 av = *(const float2*)&A[(row0 + li) * EMB + kt + lk];
        As[li * 18 + lk] = av.x;
        As[li * 18 + lk + 1] = av.y;
#pragma unroll
        for (int i = 0; i < 4; i++) {
            int idx = tid + i * 512;
            if (idx < 1600) {
                int e = idx / 100, h2 = (idx - e * 100) * 2;
                float2 bv = *(const float2*)&g_WbqeT[(size_t)(kt + e) * 200 + h2];
                Bs[h2 * 18 + e] = bv.x;
                Bs[(h2 + 1) * 18 + e] = bv.y;
            }
        }
        __syncthreads();
#pragma unroll
        for (int kp = 0; kp < 8; kp++) {
            u64 a2 = *(const u64*)&As[r * 18 + 2 * kp];
#pragma unroll
            for (int c = 0; c < 25; c++) {
                u64 b2 = *(const u64*)&Bs[(cbase + c) * 18 + 2 * kp];
                ffma2(acc[c], a2, b2);
            }
        }
        __syncthreads();
    }
#pragma unroll
    for (int c = 0; c < 25; c++)
        g_obs_proj[(row0 + r) * BEL + cbase + c] = hsum2(acc[c]) + b_bq[cbase + c];
}

// ---------------------------------------------------------------------------
// Persistent scan kernel: 128 blocks x 640 threads; block owns 8 batch rows
// for all 50 timesteps. Carries live in shared memory.
// ---------------------------------------------------------------------------
__global__ __launch_bounds__(640, 1) void k_scan(
    const float* __restrict__ actions, const float* __restrict__ nonterm,
    const float* __restrict__ prev_state, const float* __restrict__ prev_belief,
    const float* __restrict__ noise_p, const float* __restrict__ noise_q,
    const float* __restrict__ b_sa, const float* __restrict__ b_ih,
    const float* __restrict__ b_hh, const float* __restrict__ b_bp,
    const float* __restrict__ b_sp, const float* __restrict__ b_sq,
    float* __restrict__ out) {
    extern __shared__ float sm[];
    float* sa   = sm;            // 8*40   = 320
    float* hid  = sa + 320;      // 8*200  = 1600
    float* bel  = hid + 1600;    // 8*200  = 1600
    float* gi   = bel + 1600;    // 8*600  = 4800
    float* gh   = gi + 4800;     // 8*600  = 4800
    float* hp   = gh + 4800;     // 8*200  = 1600
    float* hq   = hp + 1600;     // 8*200  = 1600
    float* part = hq + 1600;     // 5*8*120= 4800
    float* so   = part + 4800;   // 8*120  = 960
    float* post = so + 960;      // 8*30   = 240

    const int tid = threadIdx.x;
    const int b0 = blockIdx.x * 8;

    // hoist biases into registers (thread roles are fixed across t)
    float r_bsa = 0.f, r_bir = 0.f, r_biz = 0.f, r_bin = 0.f;
    float r_bhr = 0.f, r_bhz = 0.f, r_bhn = 0.f, r_bbp = 0.f, r_bo = 0.f;
    if (tid < 200) {
        r_bsa = b_sa[tid];
        r_bir = b_ih[tid]; r_biz = b_ih[200 + tid]; r_bin = b_ih[400 + tid];
        r_bhr = b_hh[tid]; r_bhz = b_hh[200 + tid]; r_bhn = b_hh[400 + tid];
        r_bbp = b_bp[tid];
    }
    if (tid < 120) r_bo = (tid < 60) ? b_sp[tid] : b_sq[tid - 60];

    // init carries
    for (int idx = tid; idx < 8 * BEL; idx += 640) {
        int bb = idx / BEL, j = idx - bb * BEL;
        bel[idx] = prev_belief[(size_t)(b0 + bb) * BEL + j];
    }
    if (tid < 240) {
        int bb = tid / 30, i = tid - bb * 30;
        post[tid] = prev_state[(size_t)(b0 + bb) * ST + i];
    }
    __syncthreads();

    for (int t = 0; t < TT; t++) {
        // ---- P0: build [s*nt | a | 0 0] rows ----
        if (tid < 320) {
            int bb = tid / 40, c = tid - bb * 40;
            int row = b0 + bb;
            float v = 0.f;
            if (c < 30)       v = post[bb * 30 + c] * nonterm[(size_t)t * BB + row];
            else if (c < 38)  v = actions[((size_t)t * BB + row) * ACT + (c - 30)];
            sa[bb * 40 + c] = v;
        }
        __syncthreads();

        // ---- P1: hidden = relu(sa @ Wsa^T + b_sa) ----
        if (tid < 200) {
            u64 acc[8];
#pragma unroll
            for (int bb = 0; bb < 8; bb++) acc[bb] = 0ULL;
#pragma unroll
            for (int k4 = 0; k4 < 10; k4++) {
                ulonglong2 w = __ldg((const ulonglong2*)&g_Wsa4[(k4 * 200 + tid) << 2]);
#pragma unroll
                for (int bb = 0; bb < 8; bb++) {
                    ulonglong2 s = *(const ulonglong2*)&sa[bb * 40 + k4 * 4];
                    ffma2(acc[bb], s.x, w.x);
                    ffma2(acc[bb], s.y, w.y);
                }
            }
#pragma unroll
            for (int bb = 0; bb < 8; bb++)
                hid[bb * 200 + tid] = fmaxf(hsum2(acc[bb]) + r_bsa, 0.f);
        }
        __syncthreads();

        // ---- P2a: gi = hid @ W_ih^T ----
        if (tid < 600) {
            {
                u64 acc[8];
#pragma unroll
                for (int bb = 0; bb < 8; bb++) acc[bb] = 0ULL;
                ulonglong2 w = __ldg((const ulonglong2*)&g_Wg4[(0 * 1200 + tid) << 2]);
#pragma unroll 2
                for (int k4 = 0; k4 < 50; k4++) {
                    ulonglong2 wn = w;
                    if (k4 < 49)
                        wn = __ldg((const ulonglong2*)&g_Wg4[((k4 + 1) * 1200 + tid) << 2]);
#pragma unroll
                    for (int bb = 0; bb < 8; bb++) {
                        ulonglong2 h = *(const ulonglong2*)&hid[bb * 200 + k4 * 4];
                        ffma2(acc[bb], h.x, w.x);
                        ffma2(acc[bb], h.y, w.y);
                    }
                    w = wn;
                }
#pragma unroll
                for (int bb = 0; bb < 8; bb++) gi[bb * 600 + tid] = hsum2(acc[bb]);
            }
            // ---- P2b: gh = bel @ W_hh^T ----
            {
                u64 acc[8];
#pragma unroll
                for (int bb = 0; bb < 8; bb++) acc[bb] = 0ULL;
                ulonglong2 w = __ldg((const ulonglong2*)&g_Wg4[(0 * 1200 + 600 + tid) << 2]);
#pragma unroll 2
                for (int k4 = 0; k4 < 50; k4++) {
                    ulonglong2 wn = w;
                    if (k4 < 49)
                        wn = __ldg((const ulonglong2*)&g_Wg4[((k4 + 1) * 1200 + 600 + tid) << 2]);
#pragma unroll
                    for (int bb = 0; bb < 8; bb++) {
                        ulonglong2 h = *(const ulonglong2*)&bel[bb * 200 + k4 * 4];
                        ffma2(acc[bb], h.x, w.x);
                        ffma2(acc[bb], h.y, w.y);
                    }
                    w = wn;
                }
#pragma unroll
                for (int bb = 0; bb < 8; bb++) gh[bb * 600 + tid] = hsum2(acc[bb]);
            }
        }
        __syncthreads();

        // ---- P3: GRU combine, new belief ----
        if (tid < 200) {
#pragma unroll
            for (int bb = 0; bb < 8; bb++) {
                float gir = gi[bb * 600 + tid], giz = gi[bb * 600 + 200 + tid],
                      gin = gi[bb * 600 + 400 + tid];
                float ghr = gh[bb * 600 + tid], ghz = gh[bb * 600 + 200 + tid],
                      ghn = gh[bb * 600 + 400 + tid];
                float r = sigm(gir + r_bir + ghr + r_bhr);
                float z = sigm(giz + r_biz + ghz + r_bhz);
                float n = tanhfast(gin + r_bin + r * (ghn + r_bhn));
                float bv = bel[bb * 200 + tid];
                float nb = (1.f - z) * n + z * bv;
                bel[bb * 200 + tid] = nb;
                out[OFF_B + ((size_t)t * BB + b0 + bb) * BEL + tid] = nb;
            }
        }
        __syncthreads();

        // ---- P4: hp = relu(bel@Wbp+b), hq = relu(bel@Wbqb + obs_proj) ----
        if (tid < 400) {
            u64 acc[8];
#pragma unroll
            for (int bb = 0; bb < 8; bb++) acc[bb] = 0ULL;
            ulonglong2 w = __ldg((const ulonglong2*)&g_Wh4[(0 * 400 + tid) << 2]);
#pragma unroll 2
            for (int k4 = 0; k4 < 50; k4++) {
                ulonglong2 wn = w;
                if (k4 < 49)
                    wn = __ldg((const ulonglong2*)&g_Wh4[((k4 + 1) * 400 + tid) << 2]);
#pragma unroll
                for (int bb = 0; bb < 8; bb++) {
                    ulonglong2 h = *(const ulonglong2*)&bel[bb * 200 + k4 * 4];
                    ffma2(acc[bb], h.x, w.x);
                    ffma2(acc[bb], h.y, w.y);
                }
                w = wn;
            }
            if (tid < 200) {
#pragma unroll
                for (int bb = 0; bb < 8; bb++)
                    hp[bb * 200 + tid] = fmaxf(hsum2(acc[bb]) + r_bbp, 0.f);
            } else {
                int j = tid - 200;
#pragma unroll
                for (int bb = 0; bb < 8; bb++) {
                    float o = g_obs_proj[((size_t)t * BB + b0 + bb) * BEL + j];
                    hq[bb * 200 + j] = fmaxf(hsum2(acc[bb]) + o, 0.f);
                }
            }
        }
        __syncthreads();

        // ---- P5a: partial head projections (split k 5 ways) ----
        if (tid < 600) {
            int g = tid % 120, q = tid / 120;
            const float* src = (g < 60) ? hp : hq;
            u64 acc[8];
#pragma unroll
            for (int bb = 0; bb < 8; bb++) acc[bb] = 0ULL;
#pragma unroll
            for (int kk = 0; kk < 10; kk++) {
                int k4 = q * 10 + kk;
                ulonglong2 w = __ldg((const ulonglong2*)&g_Wo4[(k4 * 120 + g) << 2]);
#pragma unroll
                for (int bb = 0; bb < 8; bb++) {
                    ulonglong2 h = *(const ulonglong2*)&src[bb * 200 + k4 * 4];
                    ffma2(acc[bb], h.x, w.x);
                    ffma2(acc[bb], h.y, w.y);
                }
            }
#pragma unroll
            for (int bb = 0; bb < 8; bb++)
                part[q * 960 + bb * 120 + g] = hsum2(acc[bb]);
        }
        __syncthreads();

        // ---- P5b: reduce 5 partials ----
        if (tid < 120) {
#pragma unroll
            for (int bb = 0; bb < 8; bb++) {
                float s = r_bo;
#pragma unroll
                for (int q = 0; q < 5; q++) s += part[q * 960 + bb * 120 + tid];
                so[bb * 120 + tid] = s;
            }
        }
        __syncthreads();

        // ---- P6: sample, write outputs, update post carry ----
        if (tid < 240) {
            int bb = tid / 30, i = tid - bb * 30;
            size_t gidx = ((size_t)t * BB + b0 + bb) * ST + i;
            float mp  = so[bb * 120 + i];
            float spv = softplusf(so[bb * 120 + 30 + i]) + 0.1f;
            out[OFF_MP + gidx] = mp;
            out[OFF_SP + gidx] = spv;
            out[OFF_PS + gidx] = fmaf(spv, noise_p[gidx], mp);
            float mq  = so[bb * 120 + 60 + i];
            float sqv = softplusf(so[bb * 120 + 90 + i]) + 0.1f;
            float po  = fmaf(sqv, noise_q[gidx], mq);
            out[OFF_MQ + gidx] = mq;
            out[OFF_SQ + gidx] = sqv;
            out[OFF_PO + gidx] = po;
            post[bb * 30 + i] = po;
        }
        __syncthreads();
    }
}

#define SCAN_SMEM (22320 * 4)

// ---------------------------------------------------------------------------
extern "C" void kernel_launch(void* const* d_in, const int* in_sizes, int n_in,
                              void* d_out, int out_size) {
    const float* prev_state   = (const float*)d_in[0];
    const float* actions      = (const float*)d_in[1];
    const float* prev_belief  = (const float*)d_in[2];
    const float* observations = (const float*)d_in[3];
    const float* nonterm      = (const float*)d_in[4];
    const float* noise_p      = (const float*)d_in[5];
    const float* noise_q      = (const float*)d_in[6];
    const float* W_sa = (const float*)d_in[7];  const float* b_sa = (const float*)d_in[8];
    const float* W_ih = (const float*)d_in[9];  const float* b_ih = (const float*)d_in[10];
    const float* W_hh = (const float*)d_in[11]; const float* b_hh = (const float*)d_in[12];
    const float* W_bp = (const float*)d_in[13]; const float* b_bp = (const float*)d_in[14];
    const float* W_sp = (const float*)d_in[15]; const float* b_sp = (const float*)d_in[16];
    const float* W_bq = (const float*)d_in[17]; const float* b_bq = (const float*)d_in[18];
    const float* W_sq = (const float*)d_in[19]; const float* b_sq = (const float*)d_in[20];
    float* out = (float*)d_out;
    (void)in_sizes; (void)n_in; (void)out_size;

    static int smem_set = 0;
    if (!smem_set) {
        cudaFuncSetAttribute(k_scan, cudaFuncAttributeMaxDynamicSharedMemorySize, SCAN_SMEM);
        smem_set = 1;
    }

    k_prep<<<(PREP_N + 255) / 256, 256>>>(W_sa, W_ih, W_hh, W_bp, W_sp, W_bq, W_sq);
    k_obs_gemm<<<(TT * BB) / 64, 512>>>(observations, b_bq);
    k_scan<<<BB / 8, 640, SCAN_SMEM>>>(actions, nonterm, prev_state, prev_belief,
                                       noise_p, noise_q, b_sa, b_ih, b_hh,
                                       b_bp, b_sp, b_sq, out);
}

// round 3
// speedup vs baseline: 2.2194x; 1.3250x over previous
#include <cuda_runtime.h>
#include <math.h>

#define TT  50
#define BB  1024
#define BEL 200
#define ST  30
#define ACT 8
#define EMB 1024

// ---- output layout ----
static const size_t OFF_B  = 0;
static const size_t OFF_PS = (size_t)TT * BB * BEL;
static const size_t SZ30   = (size_t)TT * BB * ST;
static const size_t OFF_MP = OFF_PS + SZ30;
static const size_t OFF_SP = OFF_MP + SZ30;
static const size_t OFF_PO = OFF_SP + SZ30;
static const size_t OFF_MQ = OFF_PO + SZ30;
static const size_t OFF_SQ = OFF_MQ + SZ30;

// ---- device scratch ----
__device__ __align__(16) float g_obs[(size_t)TT * BB * BEL];   // obs@Wbq_e^T + b_bq
__device__ __align__(16) float g_act[(size_t)TT * BB * BEL];   // a@Wsa_a^T + b_sa
// packed weights
__device__ __align__(16) float g_Wg2[50 * 600 * 8];   // [k4][tc(600)][2cols][4k]; tc<300: gi, else gh
__device__ __align__(16) float g_Wsa[8 * 200 * 4];    // [k4][j][4k]  (state part only, k padded 30->32)
__device__ __align__(16) float g_Wh2[50 * 200 * 8];   // [k4][p(200)][2cols][4k]; p<100: Wbp, else Wbq_b
__device__ __align__(16) float g_Wo4[50 * 120 * 4];   // [k4][g(120)][4k]; g<60: Wsp else Wsq

typedef unsigned long long u64;

__device__ __forceinline__ void ffma2(u64& acc, u64 a, u64 b) {
    asm("fma.rn.f32x2 %0, %1, %2, %0;" : "+l"(acc) : "l"(a), "l"(b));
}
__device__ __forceinline__ float hsum2(u64 v) {
    float lo, hi;
    asm("mov.b64 {%0,%1}, %2;" : "=f"(lo), "=f"(hi) : "l"(v));
    return lo + hi;
}
__device__ __forceinline__ float sigm(float x) { return 1.f / (1.f + __expf(-x)); }
__device__ __forceinline__ float tanhfast(float x) { return 1.f - 2.f / (__expf(2.f * x) + 1.f); }
__device__ __forceinline__ float softplusf(float x) {
    return fmaxf(x, 0.f) + log1pf(__expf(-fabsf(x)));
}

// ---------------------------------------------------------------------------
// Prep: packed weight layouts.
// ---------------------------------------------------------------------------
#define PREP_N (240000 + 6400 + 80000 + 24000)
__global__ void k_prep(const float* __restrict__ W_sa, const float* __restrict__ W_ih,
                       const float* __restrict__ W_hh, const float* __restrict__ W_bp,
                       const float* __restrict__ W_sp, const float* __restrict__ W_bq,
                       const float* __restrict__ W_sq) {
    int idx = blockIdx.x * blockDim.x + threadIdx.x;
    if (idx < 240000) {  // g_Wg2
        int kk = idx & 3, t1 = idx >> 2;
        int cc = t1 & 1, t2 = t1 >> 1;
        int tc = t2 % 600, k4 = t2 / 600, k = 4 * k4 + kk;
        g_Wg2[idx] = (tc < 300) ? W_ih[(2 * tc + cc) * 200 + k]
                                : W_hh[(2 * (tc - 300) + cc) * 200 + k];
        return;
    }
    idx -= 240000;
    if (idx < 6400) {  // g_Wsa
        int kk = idx & 3, t = idx >> 2;
        int j = t % 200, k4 = t / 200, k = 4 * k4 + kk;
        g_Wsa[idx] = (k < 30) ? W_sa[j * 38 + k] : 0.f;
        return;
    }
    idx -= 6400;
    if (idx < 80000) {  // g_Wh2
        int kk = idx & 3, t1 = idx >> 2;
        int cc = t1 & 1, t2 = t1 >> 1;
        int p = t2 % 200, k4 = t2 / 200, k = 4 * k4 + kk;
        g_Wh2[idx] = (p < 100) ? W_bp[(2 * p + cc) * 200 + k]
                               : W_bq[(size_t)(2 * (p - 100) + cc) * 1224 + k];
        return;
    }
    idx -= 80000;
    if (idx < 24000) {  // g_Wo4
        int kk = idx & 3, t = idx >> 2;
        int g = t % 120, k4 = t / 120, k = 4 * k4 + kk;
        g_Wo4[idx] = (g < 60) ? W_sp[g * 200 + k] : W_sq[(g - 60) * 200 + k];
    }
}

// ---------------------------------------------------------------------------
// Action projection: g_act[t,row,j] = b_sa[j] + sum_i a[t,row,i]*W_sa[j][30+i]
// ---------------------------------------------------------------------------
__global__ void k_act(const float* __restrict__ actions,
                      const float* __restrict__ W_sa, const float* __restrict__ b_sa) {
    size_t idx = (size_t)blockIdx.x * 256 + threadIdx.x;  // < 10,240,000
    int j = (int)(idx % 200);
    size_t row = idx / 200;
    float acc = b_sa[j];
#pragma unroll
    for (int i = 0; i < 8; i++)
        acc = fmaf(actions[row * 8 + i], W_sa[j * 38 + 30 + i], acc);
    g_act[idx] = acc;
}

// ---------------------------------------------------------------------------
// Obs GEMM: g_obs = obs @ Wbq_e^T + b_bq.  M=51200, N=200, K=1024.
// BM=64, BN=200, BK=16. 320 threads = 16 rowg(4 rows) x 20 colg(10 cols).
// f32x2 accumulation, double-buffered smem.
// ---------------------------------------------------------------------------
__global__ __launch_bounds__(320, 1) void k_obs_gemm(const float* __restrict__ A,
                                                     const float* __restrict__ W_bq,
                                                     const float* __restrict__ b_bq) {
    __shared__ __align__(16) float As[2][64 * 20];
    __shared__ __align__(16) float Bs[2][200 * 18];
    const int tid = threadIdx.x;
    const size_t row0 = (size_t)blockIdx.x * 64;
    const int r0 = (tid / 20) * 4;
    const int c0 = (tid % 20) * 10;

    u64 acc[4][10];
#pragma unroll
    for (int i = 0; i < 4; i++)
#pragma unroll
        for (int j = 0; j < 10; j++) acc[i][j] = 0ULL;

    const int arow = tid >> 2, ak4 = tid & 3;   // tid<256 loads A

    // prologue: stage kt=0
    if (tid < 256) {
        float4 v = *(const float4*)&A[(row0 + arow) * EMB + ak4 * 4];
        *(float4*)&As[0][arow * 20 + ak4 * 4] = v;
    }
    for (int idx = tid; idx < 800; idx += 320) {
        int col = idx >> 2, e4 = idx & 3;
        float4 v = *(const float4*)&W_bq[(size_t)col * 1224 + 200 + e4 * 4];
        Bs[0][col * 18 + e4 * 4 + 0] = v.x;
        Bs[0][col * 18 + e4 * 4 + 1] = v.y;
        Bs[0][col * 18 + e4 * 4 + 2] = v.z;
        Bs[0][col * 18 + e4 * 4 + 3] = v.w;
    }
    __syncthreads();

    for (int kti = 0; kti < 64; kti++) {
        const int cur = kti & 1;
        const bool hn = (kti + 1) < 64;
        float4 pa;
        float4 pb[3];
        int nb = 0;
        if (hn) {
            int kt = (kti + 1) * 16;
            if (tid < 256)
                pa = *(const float4*)&A[(row0 + arow) * EMB + kt + ak4 * 4];
            for (int idx = tid; idx < 800; idx += 320) {
                int col = idx >> 2, e4 = idx & 3;
                pb[nb++] = *(const float4*)&W_bq[(size_t)col * 1224 + 200 + kt + e4 * 4];
            }
        }
#pragma unroll
        for (int kp = 0; kp < 8; kp++) {
            u64 a2[4], b2[10];
#pragma unroll
            for (int i = 0; i < 4; i++)
                a2[i] = *(const u64*)&As[cur][(r0 + i) * 20 + 2 * kp];
#pragma unroll
            for (int j = 0; j < 10; j++)
                b2[j] = *(const u64*)&Bs[cur][(c0 + j) * 18 + 2 * kp];
#pragma unroll
            for (int i = 0; i < 4; i++)
#pragma unroll
                for (int j = 0; j < 10; j++) ffma2(acc[i][j], a2[i], b2[j]);
        }
        if (hn) {
            int nxt = cur ^ 1;
            if (tid < 256)
                *(float4*)&As[nxt][arow * 20 + ak4 * 4] = pa;
            nb = 0;
            for (int idx = tid; idx < 800; idx += 320) {
                int col = idx >> 2, e4 = idx & 3;
                float4 v = pb[nb++];
                Bs[nxt][col * 18 + e4 * 4 + 0] = v.x;
                Bs[nxt][col * 18 + e4 * 4 + 1] = v.y;
                Bs[nxt][col * 18 + e4 * 4 + 2] = v.z;
                Bs[nxt][col * 18 + e4 * 4 + 3] = v.w;
            }
        }
        __syncthreads();
    }
#pragma unroll
    for (int i = 0; i < 4; i++)
#pragma unroll
        for (int j = 0; j < 10; j++)
            g_obs[(row0 + r0 + i) * BEL + c0 + j] = hsum2(acc[i][j]) + b_bq[c0 + j];
}

// ---------------------------------------------------------------------------
// Persistent scan kernel: 128 blocks x 640 threads, block owns 8 rows x 50 steps.
// ---------------------------------------------------------------------------
__global__ __launch_bounds__(640, 1) void k_scan(
    const float* __restrict__ nonterm,
    const float* __restrict__ prev_state, const float* __restrict__ prev_belief,
    const float* __restrict__ noise_p, const float* __restrict__ noise_q,
    const float* __restrict__ b_ih, const float* __restrict__ b_hh,
    const float* __restrict__ b_bp, const float* __restrict__ b_sp,
    const float* __restrict__ b_sq, float* __restrict__ out) {
    extern __shared__ float sm[];
    float* s_sh = sm;              // 8*32  = 256
    float* hid  = sm + 256;        // 1600
    float* bel  = sm + 1856;       // 1600
    float* gig  = sm + 3456;       // 9600  (gi @0, gh @4800; aliased: partd / part)
    float* obs  = sm + 13056;      // 1600
    float* hp   = sm + 14656;      // 1600
    float* hq   = sm + 16256;      // 1600
    float* bias = sm + 17856;      // 120
    // total 17976 floats = 71904 B

    const int tid = threadIdx.x;
    const int b0 = blockIdx.x * 8;

    // per-role register biases
    float r_bir = 0.f, r_biz = 0.f, r_bin = 0.f, r_bhr = 0.f, r_bhz = 0.f, r_bhn = 0.f;
    float r_bbp = 0.f;
    if (tid < 200) {
        r_bir = b_ih[tid]; r_biz = b_ih[200 + tid]; r_bin = b_ih[400 + tid];
        r_bhr = b_hh[tid]; r_bhz = b_hh[200 + tid]; r_bhn = b_hh[400 + tid];
        r_bbp = b_bp[tid];
    }
    if (tid < 120) bias[tid] = (tid < 60) ? b_sp[tid] : b_sq[tid - 60];

    // init carries
    for (int idx = tid; idx < 8 * BEL; idx += 640) {
        int bb = idx / BEL, j = idx - bb * BEL;
        bel[idx] = prev_belief[(size_t)(b0 + bb) * BEL + j];
    }
    if (tid < 256) {
        int bb = tid >> 5, c = tid & 31;
        float v = 0.f;
        if (c < 30)
            v = prev_state[(size_t)(b0 + bb) * ST + c] * nonterm[b0 + bb];
        s_sh[tid] = v;
    }
    __syncthreads();

    for (int t = 0; t < TT; t++) {
        // ===== PhA: hidden (tid<200) + obs staging (200<=tid<600) =====
        if (tid < 200) {
            const int j = tid;
            float actp[8];
#pragma unroll
            for (int bb = 0; bb < 8; bb++)
                actp[bb] = g_act[((size_t)t * BB + b0 + bb) * BEL + j];
            u64 acc[8];
#pragma unroll
            for (int bb = 0; bb < 8; bb++) acc[bb] = 0ULL;
#pragma unroll
            for (int k4 = 0; k4 < 8; k4++) {
                ulonglong2 w = *(const ulonglong2*)&g_Wsa[(k4 * 200 + j) * 4];
#pragma unroll
                for (int bb = 0; bb < 8; bb++) {
                    ulonglong2 s = *(const ulonglong2*)&s_sh[bb * 32 + k4 * 4];
                    ffma2(acc[bb], s.x, w.x);
                    ffma2(acc[bb], s.y, w.y);
                }
            }
#pragma unroll
            for (int bb = 0; bb < 8; bb++)
                hid[bb * 200 + j] = fmaxf(hsum2(acc[bb]) + actp[bb], 0.f);
        } else if (tid < 600) {
            int idx = tid - 200;
            float4 v = *(const float4*)&g_obs[((size_t)t * BB + b0) * BEL + idx * 4];
            *(float4*)&obs[idx * 4] = v;
        }
        __syncthreads();

        // ===== PhB: gi + gh, 600 threads, 2 cols each, depth-2 prefetch =====
        if (tid < 600) {
            const float* src = (tid < 300) ? hid : bel;
            const ulonglong2* __restrict__ wp = (const ulonglong2*)g_Wg2 + tid * 2;
            u64 accA[8], accB[8];
#pragma unroll
            for (int bb = 0; bb < 8; bb++) { accA[bb] = 0ULL; accB[bb] = 0ULL; }
            ulonglong2 w0a = wp[0],    w0b = wp[1];
            ulonglong2 w1a = wp[1200], w1b = wp[1201];
#pragma unroll 2
            for (int k4 = 0; k4 < 50; k4++) {
                ulonglong2 wa = w0a, wb = w0b;
                w0a = w1a; w0b = w1b;
                if (k4 + 2 < 50) {
                    w1a = wp[(k4 + 2) * 1200];
                    w1b = wp[(k4 + 2) * 1200 + 1];
                }
#pragma unroll
                for (int bb = 0; bb < 8; bb++) {
                    ulonglong2 h = *(const ulonglong2*)&src[bb * 200 + k4 * 4];
                    ffma2(accA[bb], h.x, wa.x); ffma2(accA[bb], h.y, wa.y);
                    ffma2(accB[bb], h.x, wb.x); ffma2(accB[bb], h.y, wb.y);
                }
            }
            int p = (tid < 300) ? tid : tid - 300;
            float* dst = (tid < 300) ? gig : (gig + 4800);
#pragma unroll
            for (int bb = 0; bb < 8; bb++) {
                dst[bb * 600 + 2 * p]     = hsum2(accA[bb]);
                dst[bb * 600 + 2 * p + 1] = hsum2(accB[bb]);
            }
        }
        __syncthreads();

        // ===== PhC: GRU combine -> new belief =====
        if (tid < 200) {
            const int j = tid;
            const float* gh = gig + 4800;
#pragma unroll
            for (int bb = 0; bb < 8; bb++) {
                float gir = gig[bb * 600 + j], giz = gig[bb * 600 + 200 + j],
                      gin = gig[bb * 600 + 400 + j];
                float ghr = gh[bb * 600 + j], ghz = gh[bb * 600 + 200 + j],
                      ghn = gh[bb * 600 + 400 + j];
                float r = sigm(gir + r_bir + ghr + r_bhr);
                float z = sigm(giz + r_biz + ghz + r_bhz);
                float n = tanhfast(gin + r_bin + r * (ghn + r_bhn));
                float bv = bel[bb * 200 + j];
                float nb = (1.f - z) * n + z * bv;
                bel[bb * 200 + j] = nb;
                out[OFF_B + ((size_t)t * BB + b0 + bb) * BEL + j] = nb;
            }
        }
        __syncthreads();

        // ===== PhD: hp/hq partials, 400 threads = 200 col-pairs x 2 k-halves =====
        if (tid < 400) {
            const int p = tid % 200;     // col-pair: p<100 -> hp, else hq
            const int half = tid / 200;  // k4 range [half*25, half*25+25)
            const ulonglong2* __restrict__ wp = (const ulonglong2*)g_Wh2 + p * 2;
            u64 accA[8], accB[8];
#pragma unroll
            for (int bb = 0; bb < 8; bb++) { accA[bb] = 0ULL; accB[bb] = 0ULL; }
            const int kb = half * 25;
            ulonglong2 w0a = wp[(kb) * 400],     w0b = wp[(kb) * 400 + 1];
            ulonglong2 w1a = wp[(kb + 1) * 400], w1b = wp[(kb + 1) * 400 + 1];
#pragma unroll 2
            for (int kk = 0; kk < 25; kk++) {
                int k4 = kb + kk;
                ulonglong2 wa = w0a, wb = w0b;
                w0a = w1a; w0b = w1b;
                if (kk + 2 < 25) {
                    w1a = wp[(k4 + 2) * 400];
                    w1b = wp[(k4 + 2) * 400 + 1];
                }
#pragma unroll
                for (int bb = 0; bb < 8; bb++) {
                    ulonglong2 h = *(const ulonglong2*)&bel[bb * 200 + k4 * 4];
                    ffma2(accA[bb], h.x, wa.x); ffma2(accA[bb], h.y, wa.y);
                    ffma2(accB[bb], h.x, wb.x); ffma2(accB[bb], h.y, wb.y);
                }
            }
            // partd[half*3200 + bb*400 + col]
#pragma unroll
            for (int bb = 0; bb < 8; bb++) {
                gig[half * 3200 + bb * 400 + 2 * p]     = hsum2(accA[bb]);
                gig[half * 3200 + bb * 400 + 2 * p + 1] = hsum2(accB[bb]);
            }
        }
        __syncthreads();

        // ===== reduce partials -> hp/hq with relu =====
        if (tid < 400) {
            const int col = tid;
#pragma unroll
            for (int bb = 0; bb < 8; bb++) {
                float v = gig[bb * 400 + col] + gig[3200 + bb * 400 + col];
                if (col < 200)
                    hp[bb * 200 + col] = fmaxf(v + r_bbp, 0.f);
                else
                    hq[bb * 200 + col - 200] = fmaxf(v + obs[bb * 200 + col - 200], 0.f);
            }
        }
        __syncthreads();

        // ===== PhE: head projections, k-split 5 =====
        if (tid < 600) {
            const int g = tid % 120, q = tid / 120;
            const float* src = (g < 60) ? hp : hq;
            u64 acc[8];
#pragma unroll
            for (int bb = 0; bb < 8; bb++) acc[bb] = 0ULL;
#pragma unroll
            for (int kk = 0; kk < 10; kk++) {
                int k4 = q * 10 + kk;
                ulonglong2 w = *(const ulonglong2*)&g_Wo4[(k4 * 120 + g) * 4];
#pragma unroll
                for (int bb = 0; bb < 8; bb++) {
                    ulonglong2 h = *(const ulonglong2*)&src[bb * 200 + k4 * 4];
                    ffma2(acc[bb], h.x, w.x);
                    ffma2(acc[bb], h.y, w.y);
                }
            }
#pragma unroll
            for (int bb = 0; bb < 8; bb++)
                gig[q * 960 + bb * 120 + g] = hsum2(acc[bb]);
        }
        __syncthreads();

        // ===== PhF: reduce heads, sample, write outputs, build s_sh(t+1) =====
        if (tid < 240) {
            const int bb = tid / 30, i = tid - bb * 30;
            size_t gidx = ((size_t)t * BB + b0 + bb) * ST + i;
            float np = noise_p[gidx], nq = noise_q[gidx];
            float mp = bias[i], spr = bias[30 + i], mq = bias[60 + i], sqr = bias[90 + i];
#pragma unroll
            for (int q = 0; q < 5; q++) {
                mp  += gig[q * 960 + bb * 120 + i];
                spr += gig[q * 960 + bb * 120 + 30 + i];
                mq  += gig[q * 960 + bb * 120 + 60 + i];
                sqr += gig[q * 960 + bb * 120 + 90 + i];
            }
            float spv = softplusf(spr) + 0.1f;
            float sqv = softplusf(sqr) + 0.1f;
            float po  = fmaf(sqv, nq, mq);
            out[OFF_MP + gidx] = mp;
            out[OFF_SP + gidx] = spv;
            out[OFF_PS + gidx] = fmaf(spv, np, mp);
            out[OFF_MQ + gidx] = mq;
            out[OFF_SQ + gidx] = sqv;
            out[OFF_PO + gidx] = po;
            if (t + 1 < TT)
                s_sh[bb * 32 + i] = po * nonterm[(size_t)(t + 1) * BB + b0 + bb];
        }
        __syncthreads();
    }
}

#define SCAN_SMEM (17976 * 4)

// ---------------------------------------------------------------------------
extern "C" void kernel_launch(void* const* d_in, const int* in_sizes, int n_in,
                              void* d_out, int out_size) {
    const float* prev_state   = (const float*)d_in[0];
    const float* actions      = (const float*)d_in[1];
    const float* prev_belief  = (const float*)d_in[2];
    const float* observations = (const float*)d_in[3];
    const float* nonterm      = (const float*)d_in[4];
    const float* noise_p      = (const float*)d_in[5];
    const float* noise_q      = (const float*)d_in[6];
    const float* W_sa = (const float*)d_in[7];  const float* b_sa = (const float*)d_in[8];
    const float* W_ih = (const float*)d_in[9];  const float* b_ih = (const float*)d_in[10];
    const float* W_hh = (const float*)d_in[11]; const float* b_hh = (const float*)d_in[12];
    const float* W_bp = (const float*)d_in[13]; const float* b_bp = (const float*)d_in[14];
    const float* W_sp = (const float*)d_in[15]; const float* b_sp = (const float*)d_in[16];
    const float* W_bq = (const float*)d_in[17]; const float* b_bq = (const float*)d_in[18];
    const float* W_sq = (const float*)d_in[19]; const float* b_sq = (const float*)d_in[20];
    float* out = (float*)d_out;
    (void)in_sizes; (void)n_in; (void)out_size;

    static int smem_set = 0;
    if (!smem_set) {
        cudaFuncSetAttribute(k_scan, cudaFuncAttributeMaxDynamicSharedMemorySize, SCAN_SMEM);
        smem_set = 1;
    }

    k_prep<<<(PREP_N + 255) / 256, 256>>>(W_sa, W_ih, W_hh, W_bp, W_sp, W_bq, W_sq);
    k_act<<<(TT * BB * BEL) / 256, 256>>>(actions, W_sa, b_sa);
    k_obs_gemm<<<(TT * BB) / 64, 320>>>(observations, W_bq, b_bq);
    k_scan<<<BB / 8, 640, SCAN_SMEM>>>(nonterm, prev_state, prev_belief,
                                       noise_p, noise_q, b_ih, b_hh,
                                       b_bp, b_sp, b_sq, out);
}